// round 4
// baseline (speedup 1.0000x reference)
#include <cuda_runtime.h>
#include <cuda_bf16.h>

// Problem constants (fixed shapes from reference setup_inputs)
#define BB 4
#define NN 32
#define HW 307200            // 480*640
#define P4 76800             // HW/4 float4 per (b,n) plane
#define NBLKX 25             // chunk blocks along plane
#define ITERS 3              // 25 * 3 * 1024 f4 = 76800 = P4
#define NHALF 16             // masks per block (N split in 2)
#define NPAIR 128            // B*N
#define MIN_PIX 20.0f

// Deterministic per-block partials (no atomics -> identical every graph replay)
// Layout: [blk][pair] so stage-2 reads are fully coalesced across threads.
__device__ float g_psum[NBLKX * NPAIR];
__device__ float g_pcnt[NBLKX * NPAIR];

// ---------------------------------------------------------------------------
// Stage 1: masked depth sums, n-blocked for depth register reuse.
// grid = (NBLKX, BB, 2), block = 256.
// Each block: ITERS x [load 4xf4 depth once -> stream 16 masks against it].
// Depth DRAM/L2 traffic: 9.6 MB total (vs 157 MB if re-read per mask).
// ---------------------------------------------------------------------------
__global__ __launch_bounds__(256)
void rdl_stage1(const float* __restrict__ depth, const float* __restrict__ masks) {
    const int b  = blockIdx.y;
    const int n0 = blockIdx.z * NHALF;            // first mask index of this block
    const size_t chunk0 = (size_t)blockIdx.x * (ITERS * 1024) + threadIdx.x;

    const float4* __restrict__ dptr =
        reinterpret_cast<const float4*>(depth) + (size_t)b * P4 + chunk0;
    const float4* __restrict__ mptr =
        reinterpret_cast<const float4*>(masks) + ((size_t)(b * NN + n0)) * P4 + chunk0;

    float sd[NHALF], c[NHALF];
#pragma unroll
    for (int n = 0; n < NHALF; n++) { sd[n] = 0.0f; c[n] = 0.0f; }

    for (int it = 0; it < ITERS; it++) {           // NOT unrolled (I$ friendly)
        const size_t off = (size_t)it * 1024;
        // depth chunk -> registers, reused for all 16 masks
        float4 dv[4];
#pragma unroll
        for (int i = 0; i < 4; i++) dv[i] = __ldg(dptr + off + i * 256);

#pragma unroll
        for (int n = 0; n < NHALF; n++) {
            float4 mv[4];
#pragma unroll
            for (int i = 0; i < 4; i++)
                mv[i] = __ldg(mptr + (size_t)n * P4 + off + i * 256);
#pragma unroll
            for (int i = 0; i < 4; i++) {
                // branchless: FSETP + predicated FADD, no divergence
                if (mv[i].x > 0.5f) { sd[n] += dv[i].x; c[n] += 1.0f; }
                if (mv[i].y > 0.5f) { sd[n] += dv[i].y; c[n] += 1.0f; }
                if (mv[i].z > 0.5f) { sd[n] += dv[i].z; c[n] += 1.0f; }
                if (mv[i].w > 0.5f) { sd[n] += dv[i].w; c[n] += 1.0f; }
            }
        }
    }

    // Reduce all 16 (sum,cnt) pairs: warp shuffle -> shared -> 16 finalizers.
    __shared__ float ss[NHALF][8], sc[NHALF][8];
    const int w = threadIdx.x >> 5, l = threadIdx.x & 31;
#pragma unroll
    for (int n = 0; n < NHALF; n++) {
        float s = sd[n], cc = c[n];
#pragma unroll
        for (int o = 16; o > 0; o >>= 1) {
            s  += __shfl_xor_sync(0xFFFFFFFFu, s,  o);
            cc += __shfl_xor_sync(0xFFFFFFFFu, cc, o);
        }
        if (l == 0) { ss[n][w] = s; sc[n][w] = cc; }
    }
    __syncthreads();
    if (threadIdx.x < NHALF) {
        const int n = threadIdx.x;
        float S = 0.0f, C = 0.0f;
#pragma unroll
        for (int i = 0; i < 8; i++) { S += ss[n][i]; C += sc[n][i]; }
        const int p = b * NN + n0 + n;
        g_psum[blockIdx.x * NPAIR + p] = S;        // [blk][pair]
        g_pcnt[blockIdx.x * NPAIR + p] = C;
    }
}

// ---------------------------------------------------------------------------
// Stage 2: finalize. ONE block of 256 threads.
// Threads 0..127: reduce NBLKX partials of pair t (coalesced, stride NPAIR).
// All 256 threads: one relation each (B*R = 256), then block reduce.
// ---------------------------------------------------------------------------
__global__ __launch_bounds__(256)
void rdl_stage2(const int* __restrict__ subj, const int* __restrict__ obj,
                const int* __restrict__ rel,  const float* __restrict__ conf,
                float* __restrict__ out) {
    __shared__ float s_dobj[NPAIR];
    __shared__ int   s_valid[NPAIR];
    const int t = threadIdx.x;

    if (t < NPAIR) {
        float S = 0.0f, C = 0.0f;
#pragma unroll
        for (int i = 0; i < NBLKX; i++) {
            S += g_psum[i * NPAIR + t];            // coalesced across threads
            C += g_pcnt[i * NPAIR + t];
        }
        s_dobj[t]  = S / fmaxf(C, 1.0f);
        s_valid[t] = (C >= MIN_PIX) ? 1 : 0;
    }
    __syncthreads();

    // relation t: b = t / 64 (subj/obj/rel/conf laid out [B][R] contiguously)
    float tot;
    int vcnt;
    {
        const int b  = t >> 6;                     // R = 64
        const int s  = subj[t];
        const int o  = obj[t];
        const int rt = rel[t];
        const int sA = (rt == 1) ? o : s;
        const int sB = (rt == 1) ? s : o;
        const float dA = s_dobj[b * NN + sA];
        const float dB = s_dobj[b * NN + sB];
        const int v = s_valid[b * NN + sA] & s_valid[b * NN + sB];
        const float margin = (rt == 2) ? 0.3f : 0.1f;
        const float coeff  = (rt == 2) ? 1.5f : 1.0f;
        const float viol   = fmaxf(dA - dB + margin, 0.0f);
        tot  = coeff * conf[t] * (v ? 1.0f : 0.0f) * viol;
        vcnt = v;
    }

    // block reduce (256 threads)
#pragma unroll
    for (int o = 16; o > 0; o >>= 1) {
        tot  += __shfl_xor_sync(0xFFFFFFFFu, tot,  o);
        vcnt += __shfl_xor_sync(0xFFFFFFFFu, vcnt, o);
    }
    __shared__ float rs[8];
    __shared__ int   rc[8];
    const int w = t >> 5, l = t & 31;
    if (l == 0) { rs[w] = tot; rc[w] = vcnt; }
    __syncthreads();
    if (t == 0) {
        float T = 0.0f; int C = 0;
#pragma unroll
        for (int i = 0; i < 8; i++) { T += rs[i]; C += rc[i]; }
        const float cf = (float)C;
        out[0] = (C > 0) ? (T / fmaxf(cf, 1.0f)) : 0.0f;
    }
}

// ---------------------------------------------------------------------------
// kernel_launch: inputs per metadata order:
//   0: depth_pred (4*1*480*640 f32)   1: masks (4*32*480*640 f32)
//   2: subj_idx (256 i32)  3: obj_idx (256 i32)
//   4: rel_type (256 i32)  5: confidence (256 f32)
// output: 1 float (scalar loss)
// ---------------------------------------------------------------------------
extern "C" void kernel_launch(void* const* d_in, const int* in_sizes, int n_in,
                              void* d_out, int out_size) {
    const float* depth = (const float*)d_in[0];
    const float* masks = (const float*)d_in[1];
    const int*   subj  = (const int*)d_in[2];
    const int*   obj   = (const int*)d_in[3];
    const int*   rel   = (const int*)d_in[4];
    const float* conf  = (const float*)d_in[5];
    float*       out   = (float*)d_out;

    dim3 grid1(NBLKX, BB, 2);
    rdl_stage1<<<grid1, 256>>>(depth, masks);
    rdl_stage2<<<1, 256>>>(subj, obj, rel, conf, out);
}

// round 6
// speedup vs baseline: 1.1146x; 1.1146x over previous
#include <cuda_runtime.h>
#include <cuda_bf16.h>

// Problem constants (fixed shapes from reference setup_inputs)
#define BB 4
#define NN 32
#define HW 307200            // 480*640
#define P4 76800             // HW/4 float4 per (b,n) plane
#define NBLKX 25             // chunk blocks along plane
#define ITERS 3              // 25 * 3 * 1024 f4 = 76800 = P4
#define NSUB 8               // masks per block (N split in 4)
#define NZ 4                 // N / NSUB
#define NPAIR 128            // B*N
#define NBLOCKS (NBLKX * BB * NZ)   // 400
#define MIN_PIX 20.0f

// Deterministic per-block partials (each slot written by exactly one block)
// Layout: [blk][pair] so finalize reads are fully coalesced across threads.
__device__ float g_psum[NBLKX * NPAIR];
__device__ float g_pcnt[NBLKX * NPAIR];
__device__ unsigned int g_done;   // zero-init at load; finalizer resets to 0

// ---------------------------------------------------------------------------
// Fused kernel. grid = (NBLKX, BB, NZ), block = 256.
// Phase A (all blocks): masked depth sums, depth chunk held in registers and
//   reused across 8 masks (depth DRAM/L2 traffic 19.6 MB vs 157 MB naive).
// Phase B (last block only, via atomic ticket): reduce partials + relations.
// ---------------------------------------------------------------------------
__global__ __launch_bounds__(256)
void rdl_fused(const float* __restrict__ depth, const float* __restrict__ masks,
               const int* __restrict__ subj, const int* __restrict__ obj,
               const int* __restrict__ rel,  const float* __restrict__ conf,
               float* __restrict__ out) {
    const int b  = blockIdx.y;
    const int n0 = blockIdx.z * NSUB;             // first mask index of this block
    const size_t chunk0 = (size_t)blockIdx.x * (ITERS * 1024) + threadIdx.x;

    const float4* __restrict__ dptr =
        reinterpret_cast<const float4*>(depth) + (size_t)b * P4 + chunk0;
    const float4* __restrict__ mptr =
        reinterpret_cast<const float4*>(masks) + ((size_t)(b * NN + n0)) * P4 + chunk0;

    float sd[NSUB], c[NSUB];
#pragma unroll
    for (int n = 0; n < NSUB; n++) { sd[n] = 0.0f; c[n] = 0.0f; }

    for (int it = 0; it < ITERS; it++) {
        const size_t off = (size_t)it * 1024;
        // depth chunk -> registers, reused for all 8 masks
        float4 dv[4];
#pragma unroll
        for (int i = 0; i < 4; i++) dv[i] = __ldg(dptr + off + i * 256);

#pragma unroll
        for (int n = 0; n < NSUB; n++) {
            float4 mv[4];
#pragma unroll
            for (int i = 0; i < 4; i++)
                mv[i] = __ldg(mptr + (size_t)n * P4 + off + i * 256);
#pragma unroll
            for (int i = 0; i < 4; i++) {
                if (mv[i].x > 0.5f) { sd[n] += dv[i].x; c[n] += 1.0f; }
                if (mv[i].y > 0.5f) { sd[n] += dv[i].y; c[n] += 1.0f; }
                if (mv[i].z > 0.5f) { sd[n] += dv[i].z; c[n] += 1.0f; }
                if (mv[i].w > 0.5f) { sd[n] += dv[i].w; c[n] += 1.0f; }
            }
        }
    }

    // Block reduce all 8 (sum,cnt) pairs: warp shuffle -> shared -> finalizers.
    __shared__ float ss[NSUB][8], sc[NSUB][8];
    const int w = threadIdx.x >> 5, l = threadIdx.x & 31;
#pragma unroll
    for (int n = 0; n < NSUB; n++) {
        float s = sd[n], cc = c[n];
#pragma unroll
        for (int o = 16; o > 0; o >>= 1) {
            s  += __shfl_xor_sync(0xFFFFFFFFu, s,  o);
            cc += __shfl_xor_sync(0xFFFFFFFFu, cc, o);
        }
        if (l == 0) { ss[n][w] = s; sc[n][w] = cc; }
    }
    __syncthreads();
    if (threadIdx.x < NSUB) {
        const int n = threadIdx.x;
        float S = 0.0f, C = 0.0f;
#pragma unroll
        for (int i = 0; i < 8; i++) { S += ss[n][i]; C += sc[n][i]; }
        const int p = b * NN + n0 + n;
        g_psum[blockIdx.x * NPAIR + p] = S;        // [blk][pair]
        g_pcnt[blockIdx.x * NPAIR + p] = C;
    }
    __syncthreads();

    // ---- atomic ticket: last finished block runs the finalize ----
    __shared__ unsigned int s_last;
    if (threadIdx.x == 0) {
        __threadfence();                           // partials visible before ticket
        s_last = (atomicAdd(&g_done, 1u) == NBLOCKS - 1) ? 1u : 0u;
    }
    __syncthreads();
    if (s_last == 0) return;

    // ======================= Phase B: finalize (1 block) ====================
    __threadfence();                               // acquire all partials
    __shared__ float s_dobj[NPAIR];
    __shared__ int   s_valid[NPAIR];
    const int t = threadIdx.x;

    if (t < NPAIR) {
        float S = 0.0f, C = 0.0f;
#pragma unroll
        for (int i = 0; i < NBLKX; i++) {
            S += g_psum[i * NPAIR + t];            // coalesced across threads
            C += g_pcnt[i * NPAIR + t];
        }
        s_dobj[t]  = S / fmaxf(C, 1.0f);
        s_valid[t] = (C >= MIN_PIX) ? 1 : 0;
    }
    __syncthreads();

    // relation t: b = t / 64 (subj/obj/rel/conf laid out [B][R] contiguously)
    float tot;
    int vcnt;
    {
        const int rb = t >> 6;                     // R = 64
        const int s  = __ldg(&subj[t]);
        const int o  = __ldg(&obj[t]);
        const int rt = __ldg(&rel[t]);
        const int sA = (rt == 1) ? o : s;
        const int sB = (rt == 1) ? s : o;
        const float dA = s_dobj[rb * NN + sA];
        const float dB = s_dobj[rb * NN + sB];
        const int v = s_valid[rb * NN + sA] & s_valid[rb * NN + sB];
        const float margin = (rt == 2) ? 0.3f : 0.1f;
        const float coeff  = (rt == 2) ? 1.5f : 1.0f;
        const float viol   = fmaxf(dA - dB + margin, 0.0f);
        tot  = coeff * __ldg(&conf[t]) * (v ? 1.0f : 0.0f) * viol;
        vcnt = v;
    }

#pragma unroll
    for (int o = 16; o > 0; o >>= 1) {
        tot  += __shfl_xor_sync(0xFFFFFFFFu, tot,  o);
        vcnt += __shfl_xor_sync(0xFFFFFFFFu, vcnt, o);
    }
    __shared__ float rs[8];
    __shared__ int   rc[8];
    if (l == 0) { rs[w] = tot; rc[w] = vcnt; }
    __syncthreads();
    if (t == 0) {
        float T = 0.0f; int C = 0;
#pragma unroll
        for (int i = 0; i < 8; i++) { T += rs[i]; C += rc[i]; }
        out[0] = (C > 0) ? (T / fmaxf((float)C, 1.0f)) : 0.0f;
        *((volatile unsigned int*)&g_done) = 0u;   // re-arm for next graph replay
    }
}

// ---------------------------------------------------------------------------
// kernel_launch: inputs per metadata order:
//   0: depth_pred (4*1*480*640 f32)   1: masks (4*32*480*640 f32)
//   2: subj_idx (256 i32)  3: obj_idx (256 i32)
//   4: rel_type (256 i32)  5: confidence (256 f32)
// output: 1 float (scalar loss)
// ---------------------------------------------------------------------------
extern "C" void kernel_launch(void* const* d_in, const int* in_sizes, int n_in,
                              void* d_out, int out_size) {
    const float* depth = (const float*)d_in[0];
    const float* masks = (const float*)d_in[1];
    const int*   subj  = (const int*)d_in[2];
    const int*   obj   = (const int*)d_in[3];
    const int*   rel   = (const int*)d_in[4];
    const float* conf  = (const float*)d_in[5];
    float*       out   = (float*)d_out;

    dim3 grid(NBLKX, BB, NZ);
    rdl_fused<<<grid, 256>>>(depth, masks, subj, obj, rel, conf, out);
}

// round 7
// speedup vs baseline: 1.1232x; 1.0077x over previous
#include <cuda_runtime.h>
#include <cuda_bf16.h>

// Problem constants (fixed shapes from reference setup_inputs)
#define BB 4
#define NN 32
#define HW 307200            // 480*640
#define P4 76800             // HW/4 float4 per (b,n) plane
#define NBLKX 25             // chunk blocks along plane
#define ITERS 3              // 25 * 3 * 1024 f4 = 76800 = P4
#define NSUB 4               // masks per block (N split in 8)
#define NZ 8                 // N / NSUB
#define NPAIR 128            // B*N
#define NBLOCKS (NBLKX * BB * NZ)   // 800
#define MIN_PIX 20.0f

// Deterministic per-block partials (each slot written by exactly one block)
// Layout: [blk][pair] so finalize reads are fully coalesced across threads.
__device__ float g_psum[NBLKX * NPAIR];
__device__ float g_pcnt[NBLKX * NPAIR];
__device__ unsigned int g_done;   // zero-init at load; finalizer resets to 0

// ---------------------------------------------------------------------------
// Fused kernel. grid = (NBLKX, BB, NZ), block = 256.
// Phase A (all blocks): masked depth sums, depth chunk held in registers and
//   reused across 4 masks. NSUB=4 keeps regs ~44 -> 6 CTAs/SM (48 warps),
//   double the resident warps of the NSUB=8 version (occ was the binding
//   constraint: DRAM 65%, occ 32%, issue 16%).
// Phase B (last block only, via atomic ticket): reduce partials + relations.
// ---------------------------------------------------------------------------
__global__ __launch_bounds__(256)
void rdl_fused(const float* __restrict__ depth, const float* __restrict__ masks,
               const int* __restrict__ subj, const int* __restrict__ obj,
               const int* __restrict__ rel,  const float* __restrict__ conf,
               float* __restrict__ out) {
    const int b  = blockIdx.y;
    const int n0 = blockIdx.z * NSUB;             // first mask index of this block
    const size_t chunk0 = (size_t)blockIdx.x * (ITERS * 1024) + threadIdx.x;

    const float4* __restrict__ dptr =
        reinterpret_cast<const float4*>(depth) + (size_t)b * P4 + chunk0;
    const float4* __restrict__ mptr =
        reinterpret_cast<const float4*>(masks) + ((size_t)(b * NN + n0)) * P4 + chunk0;

    float sd[NSUB], c[NSUB];
#pragma unroll
    for (int n = 0; n < NSUB; n++) { sd[n] = 0.0f; c[n] = 0.0f; }

    for (int it = 0; it < ITERS; it++) {
        const size_t off = (size_t)it * 1024;
        // depth chunk -> registers, reused for all 4 masks
        float4 dv[4];
#pragma unroll
        for (int i = 0; i < 4; i++) dv[i] = __ldg(dptr + off + i * 256);

#pragma unroll
        for (int n = 0; n < NSUB; n++) {
            float4 mv[4];
#pragma unroll
            for (int i = 0; i < 4; i++)
                mv[i] = __ldg(mptr + (size_t)n * P4 + off + i * 256);
#pragma unroll
            for (int i = 0; i < 4; i++) {
                if (mv[i].x > 0.5f) { sd[n] += dv[i].x; c[n] += 1.0f; }
                if (mv[i].y > 0.5f) { sd[n] += dv[i].y; c[n] += 1.0f; }
                if (mv[i].z > 0.5f) { sd[n] += dv[i].z; c[n] += 1.0f; }
                if (mv[i].w > 0.5f) { sd[n] += dv[i].w; c[n] += 1.0f; }
            }
        }
    }

    // Block reduce all 4 (sum,cnt) pairs: warp shuffle -> shared -> finalizers.
    __shared__ float ss[NSUB][8], sc[NSUB][8];
    const int w = threadIdx.x >> 5, l = threadIdx.x & 31;
#pragma unroll
    for (int n = 0; n < NSUB; n++) {
        float s = sd[n], cc = c[n];
#pragma unroll
        for (int o = 16; o > 0; o >>= 1) {
            s  += __shfl_xor_sync(0xFFFFFFFFu, s,  o);
            cc += __shfl_xor_sync(0xFFFFFFFFu, cc, o);
        }
        if (l == 0) { ss[n][w] = s; sc[n][w] = cc; }
    }
    __syncthreads();
    if (threadIdx.x < NSUB) {
        const int n = threadIdx.x;
        float S = 0.0f, C = 0.0f;
#pragma unroll
        for (int i = 0; i < 8; i++) { S += ss[n][i]; C += sc[n][i]; }
        const int p = b * NN + n0 + n;
        g_psum[blockIdx.x * NPAIR + p] = S;        // [blk][pair]
        g_pcnt[blockIdx.x * NPAIR + p] = C;
    }
    __syncthreads();

    // ---- atomic ticket: last finished block runs the finalize ----
    __shared__ unsigned int s_last;
    if (threadIdx.x == 0) {
        __threadfence();                           // partials visible before ticket
        s_last = (atomicAdd(&g_done, 1u) == NBLOCKS - 1) ? 1u : 0u;
    }
    __syncthreads();
    if (s_last == 0) return;

    // ======================= Phase B: finalize (1 block) ====================
    __threadfence();                               // acquire all partials
    __shared__ float s_dobj[NPAIR];
    __shared__ int   s_valid[NPAIR];
    const int t = threadIdx.x;

    if (t < NPAIR) {
        float S = 0.0f, C = 0.0f;
#pragma unroll
        for (int i = 0; i < NBLKX; i++) {
            S += g_psum[i * NPAIR + t];            // coalesced across threads
            C += g_pcnt[i * NPAIR + t];
        }
        s_dobj[t]  = S / fmaxf(C, 1.0f);
        s_valid[t] = (C >= MIN_PIX) ? 1 : 0;
    }
    __syncthreads();

    // relation t: b = t / 64 (subj/obj/rel/conf laid out [B][R] contiguously)
    float tot;
    int vcnt;
    {
        const int rb = t >> 6;                     // R = 64
        const int s  = __ldg(&subj[t]);
        const int o  = __ldg(&obj[t]);
        const int rt = __ldg(&rel[t]);
        const int sA = (rt == 1) ? o : s;
        const int sB = (rt == 1) ? s : o;
        const float dA = s_dobj[rb * NN + sA];
        const float dB = s_dobj[rb * NN + sB];
        const int v = s_valid[rb * NN + sA] & s_valid[rb * NN + sB];
        const float margin = (rt == 2) ? 0.3f : 0.1f;
        const float coeff  = (rt == 2) ? 1.5f : 1.0f;
        const float viol   = fmaxf(dA - dB + margin, 0.0f);
        tot  = coeff * __ldg(&conf[t]) * (v ? 1.0f : 0.0f) * viol;
        vcnt = v;
    }

#pragma unroll
    for (int o = 16; o > 0; o >>= 1) {
        tot  += __shfl_xor_sync(0xFFFFFFFFu, tot,  o);
        vcnt += __shfl_xor_sync(0xFFFFFFFFu, vcnt, o);
    }
    __shared__ float rs[8];
    __shared__ int   rc[8];
    if (l == 0) { rs[w] = tot; rc[w] = vcnt; }
    __syncthreads();
    if (t == 0) {
        float T = 0.0f; int C = 0;
#pragma unroll
        for (int i = 0; i < 8; i++) { T += rs[i]; C += rc[i]; }
        out[0] = (C > 0) ? (T / fmaxf((float)C, 1.0f)) : 0.0f;
        *((volatile unsigned int*)&g_done) = 0u;   // re-arm for next graph replay
    }
}

// ---------------------------------------------------------------------------
// kernel_launch: inputs per metadata order:
//   0: depth_pred (4*1*480*640 f32)   1: masks (4*32*480*640 f32)
//   2: subj_idx (256 i32)  3: obj_idx (256 i32)
//   4: rel_type (256 i32)  5: confidence (256 f32)
// output: 1 float (scalar loss)
// ---------------------------------------------------------------------------
extern "C" void kernel_launch(void* const* d_in, const int* in_sizes, int n_in,
                              void* d_out, int out_size) {
    const float* depth = (const float*)d_in[0];
    const float* masks = (const float*)d_in[1];
    const int*   subj  = (const int*)d_in[2];
    const int*   obj   = (const int*)d_in[3];
    const int*   rel   = (const int*)d_in[4];
    const float* conf  = (const float*)d_in[5];
    float*       out   = (float*)d_out;

    dim3 grid(NBLKX, BB, NZ);
    rdl_fused<<<grid, 256>>>(depth, masks, subj, obj, rel, conf, out);
}